// round 12
// baseline (speedup 1.0000x reference)
#include <cuda_runtime.h>
#include <cuda_bf16.h>
#include <cstdint>

// LSTM(I=13,H=64,T=5)+MLP(64->64 relu ->13), B=262144.
// Round 12: R11 (shfl-free gate-pair layout, tanh.approx, mma.sync bf16 hi/lo
// 3-product) + double-buffered A tile and per-row-group named barriers:
// ONE bar.sync(1+rg, 256) per step. h written immediately into the other
// buffer (no deferred hv regs). Z aliases the dead gate-W region.

#define THREADS 512
#define CTA_ROWS 128
#define WSTR 88   // halves per k-row (176B)
#define WSTR32 44
#define ZSTR 72
#define ZSTR32 36

// byte offsets in dynamic smem
#define OFF_WHI   0         // [256][88] bf16 : 45056
#define OFF_WLO   45056
#define OFF_A0HI  90112     // [128][88] bf16 : 22528
#define OFF_A0LO  112640
#define OFF_A1HI  135168
#define OFF_A1LO  157696
#define OFF_W1HI  180224    // [64][88] bf16  : 11264
#define OFF_W1LO  191488
#define OFF_W2HI  202752    // [16][88] bf16  : 2816
#define OFF_W2LO  205568
#define OFF_BC    208384    // float [256]
#define OFF_B1    209408    // float [64]
#define OFF_B2    209664    // float [16]
#define SMEM_BYTES 209728
#define OFF_ZHI   OFF_WHI   // [128][72] bf16 (aliases dead gate-W)
#define OFF_ZLO   OFF_WLO

__device__ __forceinline__ void mma16816(float* d,
    uint32_t a0, uint32_t a1, uint32_t a2, uint32_t a3,
    uint32_t b0, uint32_t b1)
{
    asm volatile(
        "mma.sync.aligned.m16n8k16.row.col.f32.bf16.bf16.f32 "
        "{%0,%1,%2,%3}, {%4,%5,%6,%7}, {%8,%9}, {%0,%1,%2,%3};"
        : "+f"(d[0]), "+f"(d[1]), "+f"(d[2]), "+f"(d[3])
        : "r"(a0), "r"(a1), "r"(a2), "r"(a3), "r"(b0), "r"(b1));
}

__device__ __forceinline__ void bsplit(float v, unsigned short& h, unsigned short& l) {
    __nv_bfloat16 hb = __float2bfloat16(v);
    __nv_bfloat16 lb = __float2bfloat16(v - __bfloat162float(hb));
    h = __bfloat16_as_ushort(hb);
    l = __bfloat16_as_ushort(lb);
}

__device__ __forceinline__ float tanh_fast(float v) {
    float r; asm("tanh.approx.f32 %0, %1;" : "=f"(r) : "f"(v)); return r;
}
__device__ __forceinline__ float fsig(float v) {
    return fmaf(0.5f, tanh_fast(0.5f * v), 0.5f);
}

extern __shared__ char smem_raw[];

__global__ void __launch_bounds__(THREADS, 1)
lstm_hmma5_kernel(const float* __restrict__ x,
                  const float* __restrict__ W_ih,
                  const float* __restrict__ W_hh,
                  const float* __restrict__ b_ih,
                  const float* __restrict__ b_hh,
                  const float* __restrict__ W1,
                  const float* __restrict__ b1,
                  const float* __restrict__ W2,
                  const float* __restrict__ b2,
                  float* __restrict__ out,
                  int B)
{
    unsigned short* sW_hi  = (unsigned short*)(smem_raw + OFF_WHI);
    unsigned short* sW_lo  = (unsigned short*)(smem_raw + OFF_WLO);
    unsigned short* sW1_hi = (unsigned short*)(smem_raw + OFF_W1HI);
    unsigned short* sW1_lo = (unsigned short*)(smem_raw + OFF_W1LO);
    unsigned short* sW2_hi = (unsigned short*)(smem_raw + OFF_W2HI);
    unsigned short* sW2_lo = (unsigned short*)(smem_raw + OFF_W2LO);
    unsigned short* sZ_hi  = (unsigned short*)(smem_raw + OFF_ZHI);
    unsigned short* sZ_lo  = (unsigned short*)(smem_raw + OFF_ZLO);
    const uint32_t* W_hi32  = (const uint32_t*)sW_hi;
    const uint32_t* W_lo32  = (const uint32_t*)sW_lo;
    const uint32_t* W1_hi32 = (const uint32_t*)sW1_hi;
    const uint32_t* W1_lo32 = (const uint32_t*)sW1_lo;
    const uint32_t* W2_hi32 = (const uint32_t*)sW2_hi;
    const uint32_t* W2_lo32 = (const uint32_t*)sW2_lo;
    const uint32_t* Z_hi32  = (const uint32_t*)sZ_hi;
    const uint32_t* Z_lo32  = (const uint32_t*)sZ_lo;
    float* s_bc = (float*)(smem_raw + OFF_BC);
    float* s_b1 = (float*)(smem_raw + OFF_B1);
    float* s_b2 = (float*)(smem_raw + OFF_B2);

    unsigned short* aHiP[2] = {(unsigned short*)(smem_raw + OFF_A0HI),
                               (unsigned short*)(smem_raw + OFF_A1HI)};
    unsigned short* aLoP[2] = {(unsigned short*)(smem_raw + OFF_A0LO),
                               (unsigned short*)(smem_raw + OFF_A1LO)};

    const int tid  = threadIdx.x;
    const int lane = tid & 31;
    const int w    = tid >> 5;      // warp 0..15
    const int g    = lane >> 2;     // 0..7
    const int c    = lane & 3;      // 0..3
    const int rg   = w >> 3;        // row group 0..1 (64 rows each)
    const int cg   = w & 7;         // col group 0..7 (32 gate-cols each)
    const int trg  = tid & 255;     // thread id within row group
    const int b0   = blockIdx.x * CTA_ROWS;

    // ---------------- stage weights (bf16 hi/lo) ----------------
    // Gate-pair column map (shfl-free): block b=C>>4 covers neurons 4b..4b+3;
    // r=C&15: r<8 -> neuron 4b+(r>>1), gate = r&1 ? f : i
    //         r>=8 -> neuron 4b+((r-8)>>1), gate = r&1 ? o : g
    for (int idx = tid; idx < 256 * 80; idx += THREADS) {
        int C = idx / 80, k = idx % 80;
        int blk = C >> 4, r = C & 15;
        int neuron = 4 * blk + ((r & 7) >> 1);
        int gate = (r < 8) ? (r & 1) : 2 + (r & 1);
        int R = 64 * gate + neuron;
        float v = 0.0f;
        if (k < 64)      v = W_hh[R * 64 + k];
        else if (k < 77) v = W_ih[R * 13 + (k - 64)];
        unsigned short h, l; bsplit(v, h, l);
        sW_hi[C * WSTR + k] = h;
        sW_lo[C * WSTR + k] = l;
    }
    for (int idx = tid; idx < 64 * 64; idx += THREADS) {
        int j = idx >> 6, k = idx & 63;
        unsigned short h, l; bsplit(W1[j * 64 + k], h, l);
        sW1_hi[j * WSTR + k] = h;
        sW1_lo[j * WSTR + k] = l;
    }
    for (int idx = tid; idx < 16 * 64; idx += THREADS) {
        int p = idx >> 6, k = idx & 63;
        float v = (p < 13) ? W2[p * 64 + k] : 0.0f;
        unsigned short h, l; bsplit(v, h, l);
        sW2_hi[p * WSTR + k] = h;
        sW2_lo[p * WSTR + k] = l;
    }
    for (int idx = tid; idx < 256; idx += THREADS) {
        int blk = idx >> 4, r = idx & 15;
        int neuron = 4 * blk + ((r & 7) >> 1);
        int gate = (r < 8) ? (r & 1) : 2 + (r & 1);
        int R = 64 * gate + neuron;
        s_bc[idx] = b_ih[R] + b_hh[R];
    }
    if (tid < 64) s_b1[tid] = b1[tid];
    if (tid < 16) s_b2[tid] = (tid < 13) ? b2[tid] : 0.0f;

    // zero BOTH A buffers (h0 = 0; pads k77..79 stay 0 forever)
    {
        uint32_t* A0 = (uint32_t*)(smem_raw + OFF_A0HI);
        for (int idx = tid; idx < 4 * CTA_ROWS * WSTR32; idx += THREADS)
            A0[idx] = 0;
    }
    __syncthreads();

    // x(t=0) into buffer 0 at k = 64+i (rg-local rows)
    for (int s = 0; s < 4; s++) {
        int idx = trg + s * 256;
        if (idx < 64 * 13) {
            int row = rg * 64 + idx / 13, i = idx % 13;
            unsigned short h, l; bsplit(x[(size_t)(b0 + row) * 65 + i], h, l);
            aHiP[0][row * WSTR + 64 + i] = h;
            aLoP[0][row * WSTR + 64 + i] = l;
        }
    }

    float creg[16];
#pragma unroll
    for (int i = 0; i < 16; i++) creg[i] = 0.0f;

    __syncthreads();

    // ---------------- 5 recurrent steps (ONE rg-scoped barrier each) --------
#pragma unroll 1
    for (int t = 0; t < 5; t++) {
        const int cur = t & 1, nxt = cur ^ 1;
        const uint32_t* A_hi32 = (const uint32_t*)aHiP[cur];
        const uint32_t* A_lo32 = (const uint32_t*)aLoP[cur];
        unsigned short* nHi = aHiP[nxt];
        unsigned short* nLo = aLoP[nxt];

        // prefetch x(t+1) (rg-local rows)
        float xf[4];
        if (t < 4) {
#pragma unroll
            for (int s = 0; s < 4; s++) {
                int idx = trg + s * 256;
                if (idx < 64 * 13) {
                    int row = rg * 64 + idx / 13, i = idx % 13;
                    xf[s] = x[(size_t)(b0 + row) * 65 + (t + 1) * 13 + i];
                }
            }
        }

#pragma unroll
        for (int p = 0; p < 2; p++) {
            float d[4][2][4];
#pragma unroll
            for (int ct = 0; ct < 2; ct++) {
                int C0 = 32 * cg + 16 * p + 8 * ct + 2 * c;
                float bx = s_bc[C0], by = s_bc[C0 + 1];
#pragma unroll
                for (int rt = 0; rt < 4; rt++) {
                    d[rt][ct][0] = bx; d[rt][ct][1] = by;
                    d[rt][ct][2] = bx; d[rt][ct][3] = by;
                }
            }

#pragma unroll
            for (int kc = 0; kc < 5; kc++) {
                uint32_t bh[2][2], bl[2][2];
#pragma unroll
                for (int ct = 0; ct < 2; ct++) {
                    int widx = (32 * cg + 16 * p + 8 * ct + g) * WSTR32 + 8 * kc + c;
                    bh[ct][0] = W_hi32[widx]; bh[ct][1] = W_hi32[widx + 4];
                    bl[ct][0] = W_lo32[widx]; bl[ct][1] = W_lo32[widx + 4];
                }
#pragma unroll
                for (int rt = 0; rt < 4; rt++) {
                    int r0w = (rg * 64 + 16 * rt + g) * WSTR32 + 8 * kc + c;
                    int r1w = r0w + 8 * WSTR32;
                    uint32_t ah0 = A_hi32[r0w],     ah1 = A_hi32[r1w];
                    uint32_t ah2 = A_hi32[r0w + 4], ah3 = A_hi32[r1w + 4];
                    uint32_t al0 = A_lo32[r0w],     al1 = A_lo32[r1w];
                    uint32_t al2 = A_lo32[r0w + 4], al3 = A_lo32[r1w + 4];
#pragma unroll
                    for (int ct = 0; ct < 2; ct++) {
                        mma16816(d[rt][ct], ah0, ah1, ah2, ah3, bh[ct][0], bh[ct][1]);
                        mma16816(d[rt][ct], ah0, ah1, ah2, ah3, bl[ct][0], bl[ct][1]);
                        mma16816(d[rt][ct], al0, al1, al2, al3, bh[ct][0], bh[ct][1]);
                    }
                }
            }

            // epilogue: all 4 gates of neuron (8cg+4p+c) in-thread; write h
            // immediately into the OTHER buffer (no read conflict).
#pragma unroll
            for (int rt = 0; rt < 4; rt++) {
#pragma unroll
                for (int j = 0; j < 2; j++) {
                    float gi = d[rt][0][2 * j], gf = d[rt][0][2 * j + 1];
                    float gg = d[rt][1][2 * j], go = d[rt][1][2 * j + 1];
                    int ci = p * 8 + rt * 2 + j;
                    float cn = fsig(gf) * creg[ci] + fsig(gi) * tanh_fast(gg);
                    creg[ci] = cn;
                    float hval = fsig(go) * tanh_fast(cn);
                    int row = rg * 64 + 16 * rt + g + 8 * j;
                    int n   = 8 * cg + 4 * p + c;
                    unsigned short h, l; bsplit(hval, h, l);
                    nHi[row * WSTR + n] = h;
                    nLo[row * WSTR + n] = l;
                }
            }
        }

        // x(t+1) into next buffer (rg-local rows)
        if (t < 4) {
#pragma unroll
            for (int s = 0; s < 4; s++) {
                int idx = trg + s * 256;
                if (idx < 64 * 13) {
                    int row = rg * 64 + idx / 13, i = idx % 13;
                    unsigned short h, l; bsplit(xf[s], h, l);
                    nHi[row * WSTR + 64 + i] = h;
                    nLo[row * WSTR + 64 + i] = l;
                }
            }
        }

        // row-group-scoped barrier: only the 8 warps sharing these rows
        asm volatile("bar.sync %0, 256;" :: "r"(1 + rg) : "memory");
    }

    // final h lives in buffer 1 (written by step t=4)
    const uint32_t* A_hi32 = (const uint32_t*)aHiP[1];
    const uint32_t* A_lo32 = (const uint32_t*)aLoP[1];

    // ---------------- MLP layer 1 via mma: z = relu(h @ W1^T + b1) ----------
    {
        const int m_cg = w & 7;      // 0..7 (8 cols)
        int col0 = 8 * m_cg + 2 * c;
        float dz[4][4];
#pragma unroll
        for (int rt = 0; rt < 4; rt++) {
            dz[rt][0] = s_b1[col0]; dz[rt][1] = s_b1[col0 + 1];
            dz[rt][2] = s_b1[col0]; dz[rt][3] = s_b1[col0 + 1];
        }
#pragma unroll
        for (int kc = 0; kc < 4; kc++) {
            int widx = (8 * m_cg + g) * WSTR32 + 8 * kc + c;
            uint32_t b1h0 = W1_hi32[widx], b1h1 = W1_hi32[widx + 4];
            uint32_t b1l0 = W1_lo32[widx], b1l1 = W1_lo32[widx + 4];
#pragma unroll
            for (int rt = 0; rt < 4; rt++) {
                int r0w = (rg * 64 + 16 * rt + g) * WSTR32 + 8 * kc + c;
                int r1w = r0w + 8 * WSTR32;
                uint32_t ah0 = A_hi32[r0w],     ah1 = A_hi32[r1w];
                uint32_t ah2 = A_hi32[r0w + 4], ah3 = A_hi32[r1w + 4];
                uint32_t al0 = A_lo32[r0w],     al1 = A_lo32[r1w];
                uint32_t al2 = A_lo32[r0w + 4], al3 = A_lo32[r1w + 4];
                mma16816(dz[rt], ah0, ah1, ah2, ah3, b1h0, b1h1);
                mma16816(dz[rt], ah0, ah1, ah2, ah3, b1l0, b1l1);
                mma16816(dz[rt], al0, al1, al2, al3, b1h0, b1h1);
            }
        }
        __syncthreads();   // ALL warps done reading gate-W before Z (alias) writes
#pragma unroll
        for (int rt = 0; rt < 4; rt++) {
            int rA = rg * 64 + 16 * rt + g, rB = rA + 8;
            unsigned short h, l;
            bsplit(fmaxf(dz[rt][0], 0.0f), h, l);
            sZ_hi[rA * ZSTR + col0] = h;     sZ_lo[rA * ZSTR + col0] = l;
            bsplit(fmaxf(dz[rt][1], 0.0f), h, l);
            sZ_hi[rA * ZSTR + col0 + 1] = h; sZ_lo[rA * ZSTR + col0 + 1] = l;
            bsplit(fmaxf(dz[rt][2], 0.0f), h, l);
            sZ_hi[rB * ZSTR + col0] = h;     sZ_lo[rB * ZSTR + col0] = l;
            bsplit(fmaxf(dz[rt][3], 0.0f), h, l);
            sZ_hi[rB * ZSTR + col0 + 1] = h; sZ_lo[rB * ZSTR + col0 + 1] = l;
        }
    }
    __syncthreads();

    // ---------------- MLP layer 2 via mma: out = z @ W2^T + b2 --------------
    {
        const int r2 = w >> 1;       // 0..7 (16 rows)
        const int c2 = w & 1;        // 0..1 (8 cols)
        int colA = 8 * c2 + 2 * c, colB = colA + 1;
        float dd[4];
        dd[0] = s_b2[colA]; dd[1] = s_b2[colB];
        dd[2] = s_b2[colA]; dd[3] = s_b2[colB];
#pragma unroll
        for (int kc = 0; kc < 4; kc++) {
            int widx = (8 * c2 + g) * WSTR32 + 8 * kc + c;
            uint32_t b2h0 = W2_hi32[widx], b2h1 = W2_hi32[widx + 4];
            uint32_t b2l0 = W2_lo32[widx], b2l1 = W2_lo32[widx + 4];
            int r0w = (16 * r2 + g) * ZSTR32 + 8 * kc + c;
            int r1w = r0w + 8 * ZSTR32;
            uint32_t ah0 = Z_hi32[r0w],     ah1 = Z_hi32[r1w];
            uint32_t ah2 = Z_hi32[r0w + 4], ah3 = Z_hi32[r1w + 4];
            uint32_t al0 = Z_lo32[r0w],     al1 = Z_lo32[r1w];
            uint32_t al2 = Z_lo32[r0w + 4], al3 = Z_lo32[r1w + 4];
            mma16816(dd, ah0, ah1, ah2, ah3, b2h0, b2h1);
            mma16816(dd, ah0, ah1, ah2, ah3, b2l0, b2l1);
            mma16816(dd, al0, al1, al2, al3, b2h0, b2h1);
        }
        int rowA = 16 * r2 + g, rowB = rowA + 8;
        if (colA < 13) {
            out[(size_t)(b0 + rowA) * 13 + colA] = dd[0];
            out[(size_t)(b0 + rowB) * 13 + colA] = dd[2];
        }
        if (colB < 13) {
            out[(size_t)(b0 + rowA) * 13 + colB] = dd[1];
            out[(size_t)(b0 + rowB) * 13 + colB] = dd[3];
        }
    }
}

extern "C" void kernel_launch(void* const* d_in, const int* in_sizes, int n_in,
                              void* d_out, int out_size)
{
    const float* x    = (const float*)d_in[0];
    const float* W_ih = (const float*)d_in[1];
    const float* W_hh = (const float*)d_in[2];
    const float* b_ih = (const float*)d_in[3];
    const float* b_hh = (const float*)d_in[4];
    const float* W1   = (const float*)d_in[5];
    const float* b1   = (const float*)d_in[6];
    const float* W2   = (const float*)d_in[7];
    const float* b2   = (const float*)d_in[8];
    float* out = (float*)d_out;

    const int B = in_sizes[0] / 65;

    cudaFuncSetAttribute(lstm_hmma5_kernel,
                         cudaFuncAttributeMaxDynamicSharedMemorySize, SMEM_BYTES);

    const int grid = B / CTA_ROWS;
    lstm_hmma5_kernel<<<grid, THREADS, SMEM_BYTES>>>(
        x, W_ih, W_hh, b_ih, b_hh, W1, b1, W2, b2, out, B);
}

// round 13
// speedup vs baseline: 1.0133x; 1.0133x over previous
#include <cuda_runtime.h>
#include <cuda_bf16.h>
#include <cstdint>

// LSTM(I=13,H=64,T=5)+MLP(64->64 relu ->13), B=262144.
// Round 13: R11 kernel (shfl-free gate-pair layout, tanh.approx, mma.sync bf16
// hi/lo 3-product, 2-pass warp tile, deferred-h epilogue) reshaped to
// 256 threads / CTA_ROWS=64 so TWO independent CTAs co-reside per SM
// (launch_bounds(256,2); smem 113984B/CTA). W1/W2/Z live in the gate-weight
// region after the recurrence (staged from gmem post-loop).

#define THREADS 256
#define CTA_ROWS 64
#define WSTR 88   // halves per k-row (176B)
#define WSTR32 44
#define ZSTR 72
#define ZSTR32 36

// byte offsets in dynamic smem (per CTA)
#define OFF_WHI   0         // [256][88] bf16 : 45056   (gate weights hi)
#define OFF_WLO   45056     //                          (gate weights lo)
#define OFF_AHI   90112     // [64][88] bf16 : 11264
#define OFF_ALO   101376
#define OFF_BC    112640    // float [256] : 1024
#define OFF_B1    113664    // float [64]  : 256
#define OFF_B2    113920    // float [16]  : 64
#define SMEM_BYTES 113984
// post-recurrence aliases into the dead gate-W region:
#define OFF_W1HI  0         // [64][88] bf16 : 11264
#define OFF_W1LO  11264
#define OFF_W2HI  22528     // [16][88] bf16 : 2816
#define OFF_W2LO  25344
#define OFF_ZHI   28160     // [64][72] bf16 : 9216
#define OFF_ZLO   37376     // ends 46592 <= 90112 (inside gate-W hi+lo) OK

__device__ __forceinline__ void mma16816(float* d,
    uint32_t a0, uint32_t a1, uint32_t a2, uint32_t a3,
    uint32_t b0, uint32_t b1)
{
    asm volatile(
        "mma.sync.aligned.m16n8k16.row.col.f32.bf16.bf16.f32 "
        "{%0,%1,%2,%3}, {%4,%5,%6,%7}, {%8,%9}, {%0,%1,%2,%3};"
        : "+f"(d[0]), "+f"(d[1]), "+f"(d[2]), "+f"(d[3])
        : "r"(a0), "r"(a1), "r"(a2), "r"(a3), "r"(b0), "r"(b1));
}

__device__ __forceinline__ void bsplit(float v, unsigned short& h, unsigned short& l) {
    __nv_bfloat16 hb = __float2bfloat16(v);
    __nv_bfloat16 lb = __float2bfloat16(v - __bfloat162float(hb));
    h = __bfloat16_as_ushort(hb);
    l = __bfloat16_as_ushort(lb);
}

__device__ __forceinline__ float tanh_fast(float v) {
    float r; asm("tanh.approx.f32 %0, %1;" : "=f"(r) : "f"(v)); return r;
}
__device__ __forceinline__ float fsig(float v) {
    return fmaf(0.5f, tanh_fast(0.5f * v), 0.5f);
}

extern __shared__ char smem_raw[];

__global__ void __launch_bounds__(THREADS, 2)
lstm_hmma6_kernel(const float* __restrict__ x,
                  const float* __restrict__ W_ih,
                  const float* __restrict__ W_hh,
                  const float* __restrict__ b_ih,
                  const float* __restrict__ b_hh,
                  const float* __restrict__ W1,
                  const float* __restrict__ b1,
                  const float* __restrict__ W2,
                  const float* __restrict__ b2,
                  float* __restrict__ out,
                  int B)
{
    unsigned short* sW_hi  = (unsigned short*)(smem_raw + OFF_WHI);
    unsigned short* sW_lo  = (unsigned short*)(smem_raw + OFF_WLO);
    unsigned short* sA_hi  = (unsigned short*)(smem_raw + OFF_AHI);
    unsigned short* sA_lo  = (unsigned short*)(smem_raw + OFF_ALO);
    const uint32_t* W_hi32  = (const uint32_t*)sW_hi;
    const uint32_t* W_lo32  = (const uint32_t*)sW_lo;
    const uint32_t* A_hi32  = (const uint32_t*)sA_hi;
    const uint32_t* A_lo32  = (const uint32_t*)sA_lo;
    float* s_bc = (float*)(smem_raw + OFF_BC);
    float* s_b1 = (float*)(smem_raw + OFF_B1);
    float* s_b2 = (float*)(smem_raw + OFF_B2);

    const int tid  = threadIdx.x;
    const int lane = tid & 31;
    const int w    = tid >> 5;      // warp 0..7
    const int g    = lane >> 2;     // 0..7
    const int c    = lane & 3;      // 0..3
    const int cg   = w;             // col group 0..7 (32 gate-cols each)
    const int b0   = blockIdx.x * CTA_ROWS;

    // ---------------- stage gate weights (bf16 hi/lo) ----------------
    // Gate-pair column map (shfl-free): block b=C>>4 covers neurons 4b..4b+3;
    // r=C&15: r<8 -> neuron 4b+(r>>1), gate = r&1 ? f : i
    //         r>=8 -> neuron 4b+((r-8)>>1), gate = r&1 ? o : g
    for (int idx = tid; idx < 256 * 80; idx += THREADS) {
        int C = idx / 80, k = idx % 80;
        int blk = C >> 4, r = C & 15;
        int neuron = 4 * blk + ((r & 7) >> 1);
        int gate = (r < 8) ? (r & 1) : 2 + (r & 1);
        int R = 64 * gate + neuron;
        float v = 0.0f;
        if (k < 64)      v = W_hh[R * 64 + k];
        else if (k < 77) v = W_ih[R * 13 + (k - 64)];
        unsigned short h, l; bsplit(v, h, l);
        sW_hi[C * WSTR + k] = h;
        sW_lo[C * WSTR + k] = l;
    }
    for (int idx = tid; idx < 256; idx += THREADS) {
        int blk = idx >> 4, r = idx & 15;
        int neuron = 4 * blk + ((r & 7) >> 1);
        int gate = (r < 8) ? (r & 1) : 2 + (r & 1);
        int R = 64 * gate + neuron;
        s_bc[idx] = b_ih[R] + b_hh[R];
    }
    if (tid < 64) s_b1[tid] = b1[tid];
    if (tid < 16) s_b2[tid] = (tid < 13) ? b2[tid] : 0.0f;

    // zero A (h part = h0 = 0, pads k77..79 stay 0)
    {
        uint32_t* Ah = (uint32_t*)sA_hi;
        uint32_t* Al = (uint32_t*)sA_lo;
        for (int idx = tid; idx < CTA_ROWS * WSTR32; idx += THREADS) {
            Ah[idx] = 0; Al[idx] = 0;
        }
    }
    __syncthreads();

    // x(t=0) into A at k = 64+i
    for (int s = 0; s < 4; s++) {
        int idx = tid + s * THREADS;
        if (idx < CTA_ROWS * 13) {
            int r = idx / 13, i = idx % 13;
            unsigned short h, l; bsplit(x[(size_t)(b0 + r) * 65 + i], h, l);
            sA_hi[r * WSTR + 64 + i] = h;
            sA_lo[r * WSTR + 64 + i] = l;
        }
    }

    float creg[16];
#pragma unroll
    for (int i = 0; i < 16; i++) creg[i] = 0.0f;

    __syncthreads();

    // ---------------- 5 recurrent steps ----------------
#pragma unroll 1
    for (int t = 0; t < 5; t++) {
        // prefetch x(t+1)
        float xf[4];
        if (t < 4) {
#pragma unroll
            for (int s = 0; s < 4; s++) {
                int idx = tid + s * THREADS;
                if (idx < CTA_ROWS * 13) {
                    int r = idx / 13, i = idx % 13;
                    xf[s] = x[(size_t)(b0 + r) * 65 + (t + 1) * 13 + i];
                }
            }
        }

        float hv[16];   // index = p*8 + rt*2 + j(rowhalf)

#pragma unroll
        for (int p = 0; p < 2; p++) {
            float d[4][2][4];
#pragma unroll
            for (int ct = 0; ct < 2; ct++) {
                int C0 = 32 * cg + 16 * p + 8 * ct + 2 * c;
                float bx = s_bc[C0], by = s_bc[C0 + 1];
#pragma unroll
                for (int rt = 0; rt < 4; rt++) {
                    d[rt][ct][0] = bx; d[rt][ct][1] = by;
                    d[rt][ct][2] = bx; d[rt][ct][3] = by;
                }
            }

#pragma unroll
            for (int kc = 0; kc < 5; kc++) {
                uint32_t bh[2][2], bl[2][2];
#pragma unroll
                for (int ct = 0; ct < 2; ct++) {
                    int widx = (32 * cg + 16 * p + 8 * ct + g) * WSTR32 + 8 * kc + c;
                    bh[ct][0] = W_hi32[widx]; bh[ct][1] = W_hi32[widx + 4];
                    bl[ct][0] = W_lo32[widx]; bl[ct][1] = W_lo32[widx + 4];
                }
#pragma unroll
                for (int rt = 0; rt < 4; rt++) {
                    int r0w = (16 * rt + g) * WSTR32 + 8 * kc + c;
                    int r1w = r0w + 8 * WSTR32;
                    uint32_t ah0 = A_hi32[r0w],     ah1 = A_hi32[r1w];
                    uint32_t ah2 = A_hi32[r0w + 4], ah3 = A_hi32[r1w + 4];
                    uint32_t al0 = A_lo32[r0w],     al1 = A_lo32[r1w];
                    uint32_t al2 = A_lo32[r0w + 4], al3 = A_lo32[r1w + 4];
#pragma unroll
                    for (int ct = 0; ct < 2; ct++) {
                        mma16816(d[rt][ct], ah0, ah1, ah2, ah3, bh[ct][0], bh[ct][1]);
                        mma16816(d[rt][ct], ah0, ah1, ah2, ah3, bl[ct][0], bl[ct][1]);
                        mma16816(d[rt][ct], al0, al1, al2, al3, bh[ct][0], bh[ct][1]);
                    }
                }
            }

            // epilogue compute: all 4 gates of neuron (8cg+4p+c) in-thread
#pragma unroll
            for (int rt = 0; rt < 4; rt++) {
#pragma unroll
                for (int j = 0; j < 2; j++) {
                    float gi = d[rt][0][2 * j], gf = d[rt][0][2 * j + 1];
                    float gg = d[rt][1][2 * j], go = d[rt][1][2 * j + 1];
                    int ci = p * 8 + rt * 2 + j;
                    float cn = fsig(gf) * creg[ci] + fsig(gi) * tanh_fast(gg);
                    creg[ci] = cn;
                    hv[ci] = fsig(go) * tanh_fast(cn);
                }
            }
        }

        __syncthreads();   // all A reads (both passes, all warps) complete

        // deferred h writes: row = 16rt+g+8j, neuron n = 8cg+4p+c
#pragma unroll
        for (int p = 0; p < 2; p++) {
#pragma unroll
            for (int rt = 0; rt < 4; rt++) {
#pragma unroll
                for (int j = 0; j < 2; j++) {
                    int row = 16 * rt + g + 8 * j;
                    int n   = 8 * cg + 4 * p + c;
                    unsigned short h, l; bsplit(hv[p * 8 + rt * 2 + j], h, l);
                    sA_hi[row * WSTR + n] = h;
                    sA_lo[row * WSTR + n] = l;
                }
            }
        }
        if (t < 4) {
#pragma unroll
            for (int s = 0; s < 4; s++) {
                int idx = tid + s * THREADS;
                if (idx < CTA_ROWS * 13) {
                    int r = idx / 13, i = idx % 13;
                    unsigned short h, l; bsplit(xf[s], h, l);
                    sA_hi[r * WSTR + 64 + i] = h;
                    sA_lo[r * WSTR + 64 + i] = l;
                }
            }
        }
        __syncthreads();
    }

    // ---------------- stage W1/W2 into the dead gate-W region ---------------
    {
        unsigned short* sW1_hi = (unsigned short*)(smem_raw + OFF_W1HI);
        unsigned short* sW1_lo = (unsigned short*)(smem_raw + OFF_W1LO);
        unsigned short* sW2_hi = (unsigned short*)(smem_raw + OFF_W2HI);
        unsigned short* sW2_lo = (unsigned short*)(smem_raw + OFF_W2LO);
        for (int idx = tid; idx < 64 * 64; idx += THREADS) {
            int j = idx >> 6, k = idx & 63;
            unsigned short h, l; bsplit(W1[j * 64 + k], h, l);
            sW1_hi[j * WSTR + k] = h;
            sW1_lo[j * WSTR + k] = l;
        }
        for (int idx = tid; idx < 16 * 64; idx += THREADS) {
            int p = idx >> 6, k = idx & 63;
            float v = (p < 13) ? W2[p * 64 + k] : 0.0f;
            unsigned short h, l; bsplit(v, h, l);
            sW2_hi[p * WSTR + k] = h;
            sW2_lo[p * WSTR + k] = l;
        }
    }
    __syncthreads();

    const uint32_t* W1_hi32 = (const uint32_t*)(smem_raw + OFF_W1HI);
    const uint32_t* W1_lo32 = (const uint32_t*)(smem_raw + OFF_W1LO);
    const uint32_t* W2_hi32 = (const uint32_t*)(smem_raw + OFF_W2HI);
    const uint32_t* W2_lo32 = (const uint32_t*)(smem_raw + OFF_W2LO);
    unsigned short* sZ_hi = (unsigned short*)(smem_raw + OFF_ZHI);
    unsigned short* sZ_lo = (unsigned short*)(smem_raw + OFF_ZLO);
    const uint32_t* Z_hi32 = (const uint32_t*)sZ_hi;
    const uint32_t* Z_lo32 = (const uint32_t*)sZ_lo;

    // ---------------- MLP layer 1 via mma: z = relu(h @ W1^T + b1) ----------
    {
        int col0 = 8 * cg + 2 * c;
        float dz[4][4];
#pragma unroll
        for (int rt = 0; rt < 4; rt++) {
            dz[rt][0] = s_b1[col0]; dz[rt][1] = s_b1[col0 + 1];
            dz[rt][2] = s_b1[col0]; dz[rt][3] = s_b1[col0 + 1];
        }
#pragma unroll
        for (int kc = 0; kc < 4; kc++) {
            int widx = (8 * cg + g) * WSTR32 + 8 * kc + c;
            uint32_t b1h0 = W1_hi32[widx], b1h1 = W1_hi32[widx + 4];
            uint32_t b1l0 = W1_lo32[widx], b1l1 = W1_lo32[widx + 4];
#pragma unroll
            for (int rt = 0; rt < 4; rt++) {
                int r0w = (16 * rt + g) * WSTR32 + 8 * kc + c;
                int r1w = r0w + 8 * WSTR32;
                uint32_t ah0 = A_hi32[r0w],     ah1 = A_hi32[r1w];
                uint32_t ah2 = A_hi32[r0w + 4], ah3 = A_hi32[r1w + 4];
                uint32_t al0 = A_lo32[r0w],     al1 = A_lo32[r1w];
                uint32_t al2 = A_lo32[r0w + 4], al3 = A_lo32[r1w + 4];
                mma16816(dz[rt], ah0, ah1, ah2, ah3, b1h0, b1h1);
                mma16816(dz[rt], ah0, ah1, ah2, ah3, b1l0, b1l1);
                mma16816(dz[rt], al0, al1, al2, al3, b1h0, b1h1);
            }
        }
#pragma unroll
        for (int rt = 0; rt < 4; rt++) {
            int rA = 16 * rt + g, rB = rA + 8;
            unsigned short h, l;
            bsplit(fmaxf(dz[rt][0], 0.0f), h, l);
            sZ_hi[rA * ZSTR + col0] = h;     sZ_lo[rA * ZSTR + col0] = l;
            bsplit(fmaxf(dz[rt][1], 0.0f), h, l);
            sZ_hi[rA * ZSTR + col0 + 1] = h; sZ_lo[rA * ZSTR + col0 + 1] = l;
            bsplit(fmaxf(dz[rt][2], 0.0f), h, l);
            sZ_hi[rB * ZSTR + col0] = h;     sZ_lo[rB * ZSTR + col0] = l;
            bsplit(fmaxf(dz[rt][3], 0.0f), h, l);
            sZ_hi[rB * ZSTR + col0 + 1] = h; sZ_lo[rB * ZSTR + col0 + 1] = l;
        }
    }
    __syncthreads();

    // ---------------- MLP layer 2 via mma: out = z @ W2^T + b2 --------------
    {
        const int r2 = w >> 1;       // 0..3 (16 rows each)
        const int c2 = w & 1;        // 0..1 (8 cols each)
        int colA = 8 * c2 + 2 * c, colB = colA + 1;
        float dd[4];
        dd[0] = s_b2[colA]; dd[1] = s_b2[colB];
        dd[2] = s_b2[colA]; dd[3] = s_b2[colB];
#pragma unroll
        for (int kc = 0; kc < 4; kc++) {
            int widx = (8 * c2 + g) * WSTR32 + 8 * kc + c;
            uint32_t b2h0 = W2_hi32[widx], b2h1 = W2_hi32[widx + 4];
            uint32_t b2l0 = W2_lo32[widx], b2l1 = W2_lo32[widx + 4];
            int r0w = (16 * r2 + g) * ZSTR32 + 8 * kc + c;
            int r1w = r0w + 8 * ZSTR32;
            uint32_t ah0 = Z_hi32[r0w],     ah1 = Z_hi32[r1w];
            uint32_t ah2 = Z_hi32[r0w + 4], ah3 = Z_hi32[r1w + 4];
            uint32_t al0 = Z_lo32[r0w],     al1 = Z_lo32[r1w];
            uint32_t al2 = Z_lo32[r0w + 4], al3 = Z_lo32[r1w + 4];
            mma16816(dd, ah0, ah1, ah2, ah3, b2h0, b2h1);
            mma16816(dd, ah0, ah1, ah2, ah3, b2l0, b2l1);
            mma16816(dd, al0, al1, al2, al3, b2h0, b2h1);
        }
        int rowA = 16 * r2 + g, rowB = rowA + 8;
        if (colA < 13) {
            out[(size_t)(b0 + rowA) * 13 + colA] = dd[0];
            out[(size_t)(b0 + rowB) * 13 + colA] = dd[2];
        }
        if (colB < 13) {
            out[(size_t)(b0 + rowA) * 13 + colB] = dd[1];
            out[(size_t)(b0 + rowB) * 13 + colB] = dd[3];
        }
    }
}

extern "C" void kernel_launch(void* const* d_in, const int* in_sizes, int n_in,
                              void* d_out, int out_size)
{
    const float* x    = (const float*)d_in[0];
    const float* W_ih = (const float*)d_in[1];
    const float* W_hh = (const float*)d_in[2];
    const float* b_ih = (const float*)d_in[3];
    const float* b_hh = (const float*)d_in[4];
    const float* W1   = (const float*)d_in[5];
    const float* b1   = (const float*)d_in[6];
    const float* W2   = (const float*)d_in[7];
    const float* b2   = (const float*)d_in[8];
    float* out = (float*)d_out;

    const int B = in_sizes[0] / 65;

    cudaFuncSetAttribute(lstm_hmma6_kernel,
                         cudaFuncAttributeMaxDynamicSharedMemorySize, SMEM_BYTES);

    const int grid = B / CTA_ROWS;
    lstm_hmma6_kernel<<<grid, THREADS, SMEM_BYTES>>>(
        x, W_ih, W_hh, b_ih, b_hh, W1, b1, W2, b2, out, B);
}

// round 14
// speedup vs baseline: 1.5526x; 1.5322x over previous
#include <cuda_runtime.h>
#include <cuda_fp16.h>
#include <cstdint>

// LSTM(I=13,H=64,T=5)+MLP(64->64 relu ->13), B=262144.
// Round 14: R11 structure (shfl-free gate-pair layout, tanh.approx, 2-pass
// warp tile, deferred-h epilogue, 512 thr) with fp16 2-product emulation:
//   G ~= A*Wh + A*Wl   (W split hi/lo in fp16; A rounded once to fp16)
// 11-bit fp16 mantissa -> per-gate rel err ~1.6e-4 (vs 1e-3 gate).
// Cuts MMAs 240->160/step/warp, A-side LDS/STS traffic in half, and the
// whole A_lo / Z_lo arrays.

#define THREADS 512
#define CTA_ROWS 128
#define WSTR 88   // halves per k-row (176B)
#define WSTR32 44
#define ZSTR 72
#define ZSTR32 36

// byte offsets in dynamic smem
#define OFF_WHI   0         // [256][88] fp16 : 45056
#define OFF_WLO   45056
#define OFF_A     90112     // [128][88] fp16 : 22528
#define OFF_W1HI  112640    // [64][88] fp16  : 11264
#define OFF_W1LO  123904
#define OFF_W2HI  135168    // [16][88] fp16  : 2816
#define OFF_W2LO  137984
#define OFF_Z     140800    // [128][72] fp16 : 18432
#define OFF_BC    159232    // float [256]
#define OFF_B1    160256    // float [64]
#define OFF_B2    160512    // float [16]
#define SMEM_BYTES 160576

__device__ __forceinline__ void mma16816(float* d,
    uint32_t a0, uint32_t a1, uint32_t a2, uint32_t a3,
    uint32_t b0, uint32_t b1)
{
    asm volatile(
        "mma.sync.aligned.m16n8k16.row.col.f32.f16.f16.f32 "
        "{%0,%1,%2,%3}, {%4,%5,%6,%7}, {%8,%9}, {%0,%1,%2,%3};"
        : "+f"(d[0]), "+f"(d[1]), "+f"(d[2]), "+f"(d[3])
        : "r"(a0), "r"(a1), "r"(a2), "r"(a3), "r"(b0), "r"(b1));
}

__device__ __forceinline__ void wsplit(float v, unsigned short& h, unsigned short& l) {
    __half hb = __float2half(v);
    __half lb = __float2half(v - __half2float(hb));
    h = __half_as_ushort(hb);
    l = __half_as_ushort(lb);
}
__device__ __forceinline__ unsigned short f2h(float v) {
    return __half_as_ushort(__float2half(v));
}

__device__ __forceinline__ float tanh_fast(float v) {
    float r; asm("tanh.approx.f32 %0, %1;" : "=f"(r) : "f"(v)); return r;
}
__device__ __forceinline__ float fsig(float v) {
    return fmaf(0.5f, tanh_fast(0.5f * v), 0.5f);
}

extern __shared__ char smem_raw[];

__global__ void __launch_bounds__(THREADS, 1)
lstm_hmma7_kernel(const float* __restrict__ x,
                  const float* __restrict__ W_ih,
                  const float* __restrict__ W_hh,
                  const float* __restrict__ b_ih,
                  const float* __restrict__ b_hh,
                  const float* __restrict__ W1,
                  const float* __restrict__ b1,
                  const float* __restrict__ W2,
                  const float* __restrict__ b2,
                  float* __restrict__ out,
                  int B)
{
    unsigned short* sW_hi  = (unsigned short*)(smem_raw + OFF_WHI);
    unsigned short* sW_lo  = (unsigned short*)(smem_raw + OFF_WLO);
    unsigned short* sA     = (unsigned short*)(smem_raw + OFF_A);
    unsigned short* sW1_hi = (unsigned short*)(smem_raw + OFF_W1HI);
    unsigned short* sW1_lo = (unsigned short*)(smem_raw + OFF_W1LO);
    unsigned short* sW2_hi = (unsigned short*)(smem_raw + OFF_W2HI);
    unsigned short* sW2_lo = (unsigned short*)(smem_raw + OFF_W2LO);
    unsigned short* sZ     = (unsigned short*)(smem_raw + OFF_Z);
    const uint32_t* W_hi32  = (const uint32_t*)sW_hi;
    const uint32_t* W_lo32  = (const uint32_t*)sW_lo;
    const uint32_t* A32     = (const uint32_t*)sA;
    const uint32_t* W1_hi32 = (const uint32_t*)sW1_hi;
    const uint32_t* W1_lo32 = (const uint32_t*)sW1_lo;
    const uint32_t* W2_hi32 = (const uint32_t*)sW2_hi;
    const uint32_t* W2_lo32 = (const uint32_t*)sW2_lo;
    const uint32_t* Z32     = (const uint32_t*)sZ;
    float* s_bc = (float*)(smem_raw + OFF_BC);
    float* s_b1 = (float*)(smem_raw + OFF_B1);
    float* s_b2 = (float*)(smem_raw + OFF_B2);

    const int tid  = threadIdx.x;
    const int lane = tid & 31;
    const int w    = tid >> 5;      // warp 0..15
    const int g    = lane >> 2;     // 0..7
    const int c    = lane & 3;      // 0..3
    const int rg   = w >> 3;        // row group 0..1 (64 rows each)
    const int cg   = w & 7;         // col group 0..7 (32 gate-cols each)
    const int b0   = blockIdx.x * CTA_ROWS;

    // ---------------- stage weights (fp16, W split hi/lo) ----------------
    // Gate-pair column map (shfl-free): block b=C>>4 covers neurons 4b..4b+3;
    // r=C&15: r<8 -> neuron 4b+(r>>1), gate = r&1 ? f : i
    //         r>=8 -> neuron 4b+((r-8)>>1), gate = r&1 ? o : g
    for (int idx = tid; idx < 256 * 80; idx += THREADS) {
        int C = idx / 80, k = idx % 80;
        int blk = C >> 4, r = C & 15;
        int neuron = 4 * blk + ((r & 7) >> 1);
        int gate = (r < 8) ? (r & 1) : 2 + (r & 1);
        int R = 64 * gate + neuron;
        float v = 0.0f;
        if (k < 64)      v = W_hh[R * 64 + k];
        else if (k < 77) v = W_ih[R * 13 + (k - 64)];
        unsigned short h, l; wsplit(v, h, l);
        sW_hi[C * WSTR + k] = h;
        sW_lo[C * WSTR + k] = l;
    }
    for (int idx = tid; idx < 64 * 64; idx += THREADS) {
        int j = idx >> 6, k = idx & 63;
        unsigned short h, l; wsplit(W1[j * 64 + k], h, l);
        sW1_hi[j * WSTR + k] = h;
        sW1_lo[j * WSTR + k] = l;
    }
    for (int idx = tid; idx < 16 * 64; idx += THREADS) {
        int p = idx >> 6, k = idx & 63;
        float v = (p < 13) ? W2[p * 64 + k] : 0.0f;
        unsigned short h, l; wsplit(v, h, l);
        sW2_hi[p * WSTR + k] = h;
        sW2_lo[p * WSTR + k] = l;
    }
    for (int idx = tid; idx < 256; idx += THREADS) {
        int blk = idx >> 4, r = idx & 15;
        int neuron = 4 * blk + ((r & 7) >> 1);
        int gate = (r < 8) ? (r & 1) : 2 + (r & 1);
        int R = 64 * gate + neuron;
        s_bc[idx] = b_ih[R] + b_hh[R];
    }
    if (tid < 64) s_b1[tid] = b1[tid];
    if (tid < 16) s_b2[tid] = (tid < 13) ? b2[tid] : 0.0f;

    // zero A (h part = h0 = 0, pads k77..79 stay 0)
    {
        uint32_t* Ap = (uint32_t*)sA;
        for (int idx = tid; idx < CTA_ROWS * WSTR32; idx += THREADS) Ap[idx] = 0;
    }
    __syncthreads();

    // x(t=0) into A at k = 64+i
    for (int s = 0; s < 4; s++) {
        int idx = tid + s * THREADS;
        if (idx < CTA_ROWS * 13) {
            int r = idx / 13, i = idx % 13;
            sA[r * WSTR + 64 + i] = f2h(x[(size_t)(b0 + r) * 65 + i]);
        }
    }

    float creg[16];
#pragma unroll
    for (int i = 0; i < 16; i++) creg[i] = 0.0f;

    __syncthreads();

    // ---------------- 5 recurrent steps ----------------
#pragma unroll 1
    for (int t = 0; t < 5; t++) {
        // prefetch x(t+1)
        float xf[4];
        if (t < 4) {
#pragma unroll
            for (int s = 0; s < 4; s++) {
                int idx = tid + s * THREADS;
                if (idx < CTA_ROWS * 13) {
                    int r = idx / 13, i = idx % 13;
                    xf[s] = x[(size_t)(b0 + r) * 65 + (t + 1) * 13 + i];
                }
            }
        }

        float hv[16];   // index = p*8 + rt*2 + j(rowhalf)

#pragma unroll
        for (int p = 0; p < 2; p++) {
            float d[4][2][4];
#pragma unroll
            for (int ct = 0; ct < 2; ct++) {
                int C0 = 32 * cg + 16 * p + 8 * ct + 2 * c;
                float bx = s_bc[C0], by = s_bc[C0 + 1];
#pragma unroll
                for (int rt = 0; rt < 4; rt++) {
                    d[rt][ct][0] = bx; d[rt][ct][1] = by;
                    d[rt][ct][2] = bx; d[rt][ct][3] = by;
                }
            }

#pragma unroll
            for (int kc = 0; kc < 5; kc++) {
                uint32_t bh[2][2], bl[2][2];
#pragma unroll
                for (int ct = 0; ct < 2; ct++) {
                    int widx = (32 * cg + 16 * p + 8 * ct + g) * WSTR32 + 8 * kc + c;
                    bh[ct][0] = W_hi32[widx]; bh[ct][1] = W_hi32[widx + 4];
                    bl[ct][0] = W_lo32[widx]; bl[ct][1] = W_lo32[widx + 4];
                }
#pragma unroll
                for (int rt = 0; rt < 4; rt++) {
                    int r0w = (rg * 64 + 16 * rt + g) * WSTR32 + 8 * kc + c;
                    int r1w = r0w + 8 * WSTR32;
                    uint32_t a0 = A32[r0w],     a1 = A32[r1w];
                    uint32_t a2 = A32[r0w + 4], a3 = A32[r1w + 4];
#pragma unroll
                    for (int ct = 0; ct < 2; ct++) {
                        mma16816(d[rt][ct], a0, a1, a2, a3, bh[ct][0], bh[ct][1]);
                        mma16816(d[rt][ct], a0, a1, a2, a3, bl[ct][0], bl[ct][1]);
                    }
                }
            }

            // epilogue compute: all 4 gates of neuron (8cg+4p+c) in-thread
#pragma unroll
            for (int rt = 0; rt < 4; rt++) {
#pragma unroll
                for (int j = 0; j < 2; j++) {
                    float gi = d[rt][0][2 * j], gf = d[rt][0][2 * j + 1];
                    float gg = d[rt][1][2 * j], go = d[rt][1][2 * j + 1];
                    int ci = p * 8 + rt * 2 + j;
                    float cn = fsig(gf) * creg[ci] + fsig(gi) * tanh_fast(gg);
                    creg[ci] = cn;
                    hv[ci] = fsig(go) * tanh_fast(cn);
                }
            }
        }

        __syncthreads();   // all A reads (both passes, all warps) complete

        // deferred h writes: row = rg*64+16rt+g+8j, neuron n = 8cg+4p+c
#pragma unroll
        for (int p = 0; p < 2; p++) {
#pragma unroll
            for (int rt = 0; rt < 4; rt++) {
#pragma unroll
                for (int j = 0; j < 2; j++) {
                    int row = rg * 64 + 16 * rt + g + 8 * j;
                    int n   = 8 * cg + 4 * p + c;
                    sA[row * WSTR + n] = f2h(hv[p * 8 + rt * 2 + j]);
                }
            }
        }
        if (t < 4) {
#pragma unroll
            for (int s = 0; s < 4; s++) {
                int idx = tid + s * THREADS;
                if (idx < CTA_ROWS * 13) {
                    int r = idx / 13, i = idx % 13;
                    sA[r * WSTR + 64 + i] = f2h(xf[s]);
                }
            }
        }
        __syncthreads();
    }

    // ---------------- MLP layer 1 via mma: z = relu(h @ W1^T + b1) ----------
    {
        const int m_rg = w >> 3;     // 0..1 (64 rows)
        const int m_cg = w & 7;      // 0..7 (8 cols)
        int col0 = 8 * m_cg + 2 * c;
        float dz[4][4];
#pragma unroll
        for (int rt = 0; rt < 4; rt++) {
            dz[rt][0] = s_b1[col0]; dz[rt][1] = s_b1[col0 + 1];
            dz[rt][2] = s_b1[col0]; dz[rt][3] = s_b1[col0 + 1];
        }
#pragma unroll
        for (int kc = 0; kc < 4; kc++) {
            int widx = (8 * m_cg + g) * WSTR32 + 8 * kc + c;
            uint32_t b1h0 = W1_hi32[widx], b1h1 = W1_hi32[widx + 4];
            uint32_t b1l0 = W1_lo32[widx], b1l1 = W1_lo32[widx + 4];
#pragma unroll
            for (int rt = 0; rt < 4; rt++) {
                int r0w = (m_rg * 64 + 16 * rt + g) * WSTR32 + 8 * kc + c;
                int r1w = r0w + 8 * WSTR32;
                uint32_t a0 = A32[r0w],     a1 = A32[r1w];
                uint32_t a2 = A32[r0w + 4], a3 = A32[r1w + 4];
                mma16816(dz[rt], a0, a1, a2, a3, b1h0, b1h1);
                mma16816(dz[rt], a0, a1, a2, a3, b1l0, b1l1);
            }
        }
#pragma unroll
        for (int rt = 0; rt < 4; rt++) {
            int rA = m_rg * 64 + 16 * rt + g, rB = rA + 8;
            sZ[rA * ZSTR + col0]     = f2h(fmaxf(dz[rt][0], 0.0f));
            sZ[rA * ZSTR + col0 + 1] = f2h(fmaxf(dz[rt][1], 0.0f));
            sZ[rB * ZSTR + col0]     = f2h(fmaxf(dz[rt][2], 0.0f));
            sZ[rB * ZSTR + col0 + 1] = f2h(fmaxf(dz[rt][3], 0.0f));
        }
    }
    __syncthreads();

    // ---------------- MLP layer 2 via mma: out = z @ W2^T + b2 --------------
    {
        const int r2 = w >> 1;       // 0..7 (16 rows)
        const int c2 = w & 1;        // 0..1 (8 cols)
        int colA = 8 * c2 + 2 * c, colB = colA + 1;
        float dd[4];
        dd[0] = s_b2[colA]; dd[1] = s_b2[colB];
        dd[2] = s_b2[colA]; dd[3] = s_b2[colB];
#pragma unroll
        for (int kc = 0; kc < 4; kc++) {
            int widx = (8 * c2 + g) * WSTR32 + 8 * kc + c;
            uint32_t b2h0 = W2_hi32[widx], b2h1 = W2_hi32[widx + 4];
            uint32_t b2l0 = W2_lo32[widx], b2l1 = W2_lo32[widx + 4];
            int r0w = (16 * r2 + g) * ZSTR32 + 8 * kc + c;
            int r1w = r0w + 8 * ZSTR32;
            uint32_t a0 = Z32[r0w],     a1 = Z32[r1w];
            uint32_t a2 = Z32[r0w + 4], a3 = Z32[r1w + 4];
            mma16816(dd, a0, a1, a2, a3, b2h0, b2h1);
            mma16816(dd, a0, a1, a2, a3, b2l0, b2l1);
        }
        int rowA = 16 * r2 + g, rowB = rowA + 8;
        if (colA < 13) {
            out[(size_t)(b0 + rowA) * 13 + colA] = dd[0];
            out[(size_t)(b0 + rowB) * 13 + colA] = dd[2];
        }
        if (colB < 13) {
            out[(size_t)(b0 + rowA) * 13 + colB] = dd[1];
            out[(size_t)(b0 + rowB) * 13 + colB] = dd[3];
        }
    }
}

extern "C" void kernel_launch(void* const* d_in, const int* in_sizes, int n_in,
                              void* d_out, int out_size)
{
    const float* x    = (const float*)d_in[0];
    const float* W_ih = (const float*)d_in[1];
    const float* W_hh = (const float*)d_in[2];
    const float* b_ih = (const float*)d_in[3];
    const float* b_hh = (const float*)d_in[4];
    const float* W1   = (const float*)d_in[5];
    const float* b1   = (const float*)d_in[6];
    const float* W2   = (const float*)d_in[7];
    const float* b2   = (const float*)d_in[8];
    float* out = (float*)d_out;

    const int B = in_sizes[0] / 65;

    cudaFuncSetAttribute(lstm_hmma7_kernel,
                         cudaFuncAttributeMaxDynamicSharedMemorySize, SMEM_BYTES);

    const int grid = B / CTA_ROWS;
    lstm_hmma7_kernel<<<grid, THREADS, SMEM_BYTES>>>(
        x, W_ih, W_hh, b_ih, b_hh, W1, b1, W2, b2, out, B);
}

// round 17
// speedup vs baseline: 1.8904x; 1.2176x over previous
#include <cuda_runtime.h>
#include <cuda_fp16.h>
#include <cstdint>

// LSTM(I=13,H=64,T=5)+MLP(64->64 relu ->13), B=262144.
// Round 16 = Round 15 resubmitted verbatim (R15 bench was an infra failure:
// container died before compile/run; no kernel signal).
// Single-product pure fp16 MMA: G ~= fp16(A) * fp16(W), fp32 accumulate.
// A-rounding (R14: rel_err 1.1e-4) + same-scale W-rounding -> ~2e-4 vs 1e-3
// gate. Halves MMA count and W-side LDS; deletes all *_lo arrays.

#define THREADS 512
#define CTA_ROWS 128
#define WSTR 88   // halves per k-row (176B)
#define WSTR32 44
#define ZSTR 72
#define ZSTR32 36

// byte offsets in dynamic smem
#define OFF_W     0         // [256][88] fp16 : 45056
#define OFF_A     45056     // [128][88] fp16 : 22528
#define OFF_W1    67584     // [64][88] fp16  : 11264
#define OFF_W2    78848     // [16][88] fp16  : 2816
#define OFF_Z     81664     // [128][72] fp16 : 18432
#define OFF_BC    100096    // float [256] : 1024
#define OFF_B1    101120    // float [64]  : 256
#define OFF_B2    101376    // float [16]  : 64
#define SMEM_BYTES 101440

__device__ __forceinline__ void mma16816(float* d,
    uint32_t a0, uint32_t a1, uint32_t a2, uint32_t a3,
    uint32_t b0, uint32_t b1)
{
    asm volatile(
        "mma.sync.aligned.m16n8k16.row.col.f32.f16.f16.f32 "
        "{%0,%1,%2,%3}, {%4,%5,%6,%7}, {%8,%9}, {%0,%1,%2,%3};"
        : "+f"(d[0]), "+f"(d[1]), "+f"(d[2]), "+f"(d[3])
        : "r"(a0), "r"(a1), "r"(a2), "r"(a3), "r"(b0), "r"(b1));
}

__device__ __forceinline__ unsigned short f2h(float v) {
    return __half_as_ushort(__float2half(v));
}

__device__ __forceinline__ float tanh_fast(float v) {
    float r; asm("tanh.approx.f32 %0, %1;" : "=f"(r) : "f"(v)); return r;
}
__device__ __forceinline__ float fsig(float v) {
    return fmaf(0.5f, tanh_fast(0.5f * v), 0.5f);
}

extern __shared__ char smem_raw[];

__global__ void __launch_bounds__(THREADS, 1)
lstm_hmma8_kernel(const float* __restrict__ x,
                  const float* __restrict__ W_ih,
                  const float* __restrict__ W_hh,
                  const float* __restrict__ b_ih,
                  const float* __restrict__ b_hh,
                  const float* __restrict__ W1,
                  const float* __restrict__ b1,
                  const float* __restrict__ W2,
                  const float* __restrict__ b2,
                  float* __restrict__ out,
                  int B)
{
    unsigned short* sW  = (unsigned short*)(smem_raw + OFF_W);
    unsigned short* sA  = (unsigned short*)(smem_raw + OFF_A);
    unsigned short* sW1 = (unsigned short*)(smem_raw + OFF_W1);
    unsigned short* sW2 = (unsigned short*)(smem_raw + OFF_W2);
    unsigned short* sZ  = (unsigned short*)(smem_raw + OFF_Z);
    const uint32_t* W32  = (const uint32_t*)sW;
    const uint32_t* A32  = (const uint32_t*)sA;
    const uint32_t* W132 = (const uint32_t*)sW1;
    const uint32_t* W232 = (const uint32_t*)sW2;
    const uint32_t* Z32  = (const uint32_t*)sZ;
    float* s_bc = (float*)(smem_raw + OFF_BC);
    float* s_b1 = (float*)(smem_raw + OFF_B1);
    float* s_b2 = (float*)(smem_raw + OFF_B2);

    const int tid  = threadIdx.x;
    const int lane = tid & 31;
    const int w    = tid >> 5;      // warp 0..15
    const int g    = lane >> 2;     // 0..7
    const int c    = lane & 3;      // 0..3
    const int rg   = w >> 3;        // row group 0..1 (64 rows each)
    const int cg   = w & 7;         // col group 0..7 (32 gate-cols each)
    const int b0   = blockIdx.x * CTA_ROWS;

    // ---------------- stage weights (fp16 round-to-nearest) ----------------
    // Gate-pair column map (shfl-free): block b=C>>4 covers neurons 4b..4b+3;
    // r=C&15: r<8 -> neuron 4b+(r>>1), gate = r&1 ? f : i
    //         r>=8 -> neuron 4b+((r-8)>>1), gate = r&1 ? o : g
    for (int idx = tid; idx < 256 * 80; idx += THREADS) {
        int C = idx / 80, k = idx % 80;
        int blk = C >> 4, r = C & 15;
        int neuron = 4 * blk + ((r & 7) >> 1);
        int gate = (r < 8) ? (r & 1) : 2 + (r & 1);
        int R = 64 * gate + neuron;
        float v = 0.0f;
        if (k < 64)      v = W_hh[R * 64 + k];
        else if (k < 77) v = W_ih[R * 13 + (k - 64)];
        sW[C * WSTR + k] = f2h(v);
    }
    for (int idx = tid; idx < 64 * 64; idx += THREADS) {
        int j = idx >> 6, k = idx & 63;
        sW1[j * WSTR + k] = f2h(W1[j * 64 + k]);
    }
    for (int idx = tid; idx < 16 * 64; idx += THREADS) {
        int p = idx >> 6, k = idx & 63;
        sW2[p * WSTR + k] = f2h((p < 13) ? W2[p * 64 + k] : 0.0f);
    }
    for (int idx = tid; idx < 256; idx += THREADS) {
        int blk = idx >> 4, r = idx & 15;
        int neuron = 4 * blk + ((r & 7) >> 1);
        int gate = (r < 8) ? (r & 1) : 2 + (r & 1);
        int R = 64 * gate + neuron;
        s_bc[idx] = b_ih[R] + b_hh[R];
    }
    if (tid < 64) s_b1[tid] = b1[tid];
    if (tid < 16) s_b2[tid] = (tid < 13) ? b2[tid] : 0.0f;

    // zero A (h part = h0 = 0, pads k77..79 stay 0)
    {
        uint32_t* Ap = (uint32_t*)sA;
        for (int idx = tid; idx < CTA_ROWS * WSTR32; idx += THREADS) Ap[idx] = 0;
    }
    __syncthreads();

    // x(t=0) into A at k = 64+i
    for (int s = 0; s < 4; s++) {
        int idx = tid + s * THREADS;
        if (idx < CTA_ROWS * 13) {
            int r = idx / 13, i = idx % 13;
            sA[r * WSTR + 64 + i] = f2h(x[(size_t)(b0 + r) * 65 + i]);
        }
    }

    float creg[16];
#pragma unroll
    for (int i = 0; i < 16; i++) creg[i] = 0.0f;

    __syncthreads();

    // ---------------- 5 recurrent steps ----------------
#pragma unroll 1
    for (int t = 0; t < 5; t++) {
        // prefetch x(t+1)
        float xf[4];
        if (t < 4) {
#pragma unroll
            for (int s = 0; s < 4; s++) {
                int idx = tid + s * THREADS;
                if (idx < CTA_ROWS * 13) {
                    int r = idx / 13, i = idx % 13;
                    xf[s] = x[(size_t)(b0 + r) * 65 + (t + 1) * 13 + i];
                }
            }
        }

        float hv[16];   // index = p*8 + rt*2 + j(rowhalf)

#pragma unroll
        for (int p = 0; p < 2; p++) {
            float d[4][2][4];
#pragma unroll
            for (int ct = 0; ct < 2; ct++) {
                int C0 = 32 * cg + 16 * p + 8 * ct + 2 * c;
                float bx = s_bc[C0], by = s_bc[C0 + 1];
#pragma unroll
                for (int rt = 0; rt < 4; rt++) {
                    d[rt][ct][0] = bx; d[rt][ct][1] = by;
                    d[rt][ct][2] = bx; d[rt][ct][3] = by;
                }
            }

#pragma unroll
            for (int kc = 0; kc < 5; kc++) {
                uint32_t bh[2][2];
#pragma unroll
                for (int ct = 0; ct < 2; ct++) {
                    int widx = (32 * cg + 16 * p + 8 * ct + g) * WSTR32 + 8 * kc + c;
                    bh[ct][0] = W32[widx]; bh[ct][1] = W32[widx + 4];
                }
#pragma unroll
                for (int rt = 0; rt < 4; rt++) {
                    int r0w = (rg * 64 + 16 * rt + g) * WSTR32 + 8 * kc + c;
                    int r1w = r0w + 8 * WSTR32;
                    uint32_t a0 = A32[r0w],     a1 = A32[r1w];
                    uint32_t a2 = A32[r0w + 4], a3 = A32[r1w + 4];
#pragma unroll
                    for (int ct = 0; ct < 2; ct++) {
                        mma16816(d[rt][ct], a0, a1, a2, a3, bh[ct][0], bh[ct][1]);
                    }
                }
            }

            // epilogue compute: all 4 gates of neuron (8cg+4p+c) in-thread
#pragma unroll
            for (int rt = 0; rt < 4; rt++) {
#pragma unroll
                for (int j = 0; j < 2; j++) {
                    float gi = d[rt][0][2 * j], gf = d[rt][0][2 * j + 1];
                    float gg = d[rt][1][2 * j], go = d[rt][1][2 * j + 1];
                    int ci = p * 8 + rt * 2 + j;
                    float cn = fsig(gf) * creg[ci] + fsig(gi) * tanh_fast(gg);
                    creg[ci] = cn;
                    hv[ci] = fsig(go) * tanh_fast(cn);
                }
            }
        }

        __syncthreads();   // all A reads (both passes, all warps) complete

        // deferred h writes: row = rg*64+16rt+g+8j, neuron n = 8cg+4p+c
#pragma unroll
        for (int p = 0; p < 2; p++) {
#pragma unroll
            for (int rt = 0; rt < 4; rt++) {
#pragma unroll
                for (int j = 0; j < 2; j++) {
                    int row = rg * 64 + 16 * rt + g + 8 * j;
                    int n   = 8 * cg + 4 * p + c;
                    sA[row * WSTR + n] = f2h(hv[p * 8 + rt * 2 + j]);
                }
            }
        }
        if (t < 4) {
#pragma unroll
            for (int s = 0; s < 4; s++) {
                int idx = tid + s * THREADS;
                if (idx < CTA_ROWS * 13) {
                    int r = idx / 13, i = idx % 13;
                    sA[r * WSTR + 64 + i] = f2h(xf[s]);
                }
            }
        }
        __syncthreads();
    }

    // ---------------- MLP layer 1 via mma: z = relu(h @ W1^T + b1) ----------
    {
        const int m_rg = w >> 3;     // 0..1 (64 rows)
        const int m_cg = w & 7;      // 0..7 (8 cols)
        int col0 = 8 * m_cg + 2 * c;
        float dz[4][4];
#pragma unroll
        for (int rt = 0; rt < 4; rt++) {
            dz[rt][0] = s_b1[col0]; dz[rt][1] = s_b1[col0 + 1];
            dz[rt][2] = s_b1[col0]; dz[rt][3] = s_b1[col0 + 1];
        }
#pragma unroll
        for (int kc = 0; kc < 4; kc++) {
            int widx = (8 * m_cg + g) * WSTR32 + 8 * kc + c;
            uint32_t b1h0 = W132[widx], b1h1 = W132[widx + 4];
#pragma unroll
            for (int rt = 0; rt < 4; rt++) {
                int r0w = (m_rg * 64 + 16 * rt + g) * WSTR32 + 8 * kc + c;
                int r1w = r0w + 8 * WSTR32;
                uint32_t a0 = A32[r0w],     a1 = A32[r1w];
                uint32_t a2 = A32[r0w + 4], a3 = A32[r1w + 4];
                mma16816(dz[rt], a0, a1, a2, a3, b1h0, b1h1);
            }
        }
#pragma unroll
        for (int rt = 0; rt < 4; rt++) {
            int rA = m_rg * 64 + 16 * rt + g, rB = rA + 8;
            sZ[rA * ZSTR + col0]     = f2h(fmaxf(dz[rt][0], 0.0f));
            sZ[rA * ZSTR + col0 + 1] = f2h(fmaxf(dz[rt][1], 0.0f));
            sZ[rB * ZSTR + col0]     = f2h(fmaxf(dz[rt][2], 0.0f));
            sZ[rB * ZSTR + col0 + 1] = f2h(fmaxf(dz[rt][3], 0.0f));
        }
    }
    __syncthreads();

    // ---------------- MLP layer 2 via mma: out = z @ W2^T + b2 --------------
    {
        const int r2 = w >> 1;       // 0..7 (16 rows)
        const int c2 = w & 1;        // 0..1 (8 cols)
        int colA = 8 * c2 + 2 * c, colB = colA + 1;
        float dd[4];
        dd[0] = s_b2[colA]; dd[1] = s_b2[colB];
        dd[2] = s_b2[colA]; dd[3] = s_b2[colB];
#pragma unroll
        for (int kc = 0; kc < 4; kc++) {
            int widx = (8 * c2 + g) * WSTR32 + 8 * kc + c;
            uint32_t b2h0 = W232[widx], b2h1 = W232[widx + 4];
            int r0w = (16 * r2 + g) * ZSTR32 + 8 * kc + c;
            int r1w = r0w + 8 * ZSTR32;
            uint32_t a0 = Z32[r0w],     a1 = Z32[r1w];
            uint32_t a2 = Z32[r0w + 4], a3 = Z32[r1w + 4];
            mma16816(dd, a0, a1, a2, a3, b2h0, b2h1);
        }
        int rowA = 16 * r2 + g, rowB = rowA + 8;
        if (colA < 13) {
            out[(size_t)(b0 + rowA) * 13 + colA] = dd[0];
            out[(size_t)(b0 + rowB) * 13 + colA] = dd[2];
        }
        if (colB < 13) {
            out[(size_t)(b0 + rowA) * 13 + colB] = dd[1];
            out[(size_t)(b0 + rowB) * 13 + colB] = dd[3];
        }
    }
}

extern "C" void kernel_launch(void* const* d_in, const int* in_sizes, int n_in,
                              void* d_out, int out_size)
{
    const float* x    = (const float*)d_in[0];
    const float* W_ih = (const float*)d_in[1];
    const float* W_hh = (const float*)d_in[2];
    const float* b_ih = (const float*)d_in[3];
    const float* b_hh = (const float*)d_in[4];
    const float* W1   = (const float*)d_in[5];
    const float* b1   = (const float*)d_in[6];
    const float* W2   = (const float*)d_in[7];
    const float* b2   = (const float*)d_in[8];
    float* out = (float*)d_out;

    const int B = in_sizes[0] / 65;

    cudaFuncSetAttribute(lstm_hmma8_kernel,
                         cudaFuncAttributeMaxDynamicSharedMemorySize, SMEM_BYTES);

    const int grid = B / CTA_ROWS;
    lstm_hmma8_kernel<<<grid, THREADS, SMEM_BYTES>>>(
        x, W_ih, W_hh, b_ih, b_hh, W1, b1, W2, b2, out, B);
}